// round 10
// baseline (speedup 1.0000x reference)
#include <cuda_runtime.h>
#include <cuda_bf16.h>

// Levinson-Durbin, M=24. ONE row per thread; warp-autonomous tiles.
// KEY CHANGE (R9): rr[] is never copied to registers — the recursion reads
// its Toeplitz coefficients straight from the smem staging buffer via LDS
// (volatile to block re-registerization). This cuts live registers from
// ~56 to ~40, lifting residency 36 -> 48 warps/SM (waves 1.54 -> 1.15),
// which was the structural limiter (wave-2 residency dip blended issue
// down to 64%). LDS traffic (+300/warp, conflict-free at stride 25) and
// the fma pipe become co-bottlenecks near the same ceiling.
// out[row] = [K, a0..a23],  R a = -r1,  K = sqrt(E_24).

constexpr int M_ORD = 24;
constexpr int NC    = M_ORD + 1;               // 25
constexpr int TPB   = 64;
constexpr int WARPS = TPB / 32;                // 2
constexpr int ROWS_PER_WARP = 32;
constexpr int RPB   = TPB;                     // 64 rows per CTA (32/warp)
constexpr int WTILE_FLOATS = ROWS_PER_WARP * NC;   // 800
constexpr int WTILE_V4     = WTILE_FLOATS / 4;     // 200

__device__ __forceinline__ void cp_async16(unsigned saddr, const void* gaddr) {
    asm volatile("cp.async.cg.shared.global [%0], [%1], 16;"
                 :: "r"(saddr), "l"(gaddr));
}
__device__ __forceinline__ void cp_commit() {
    asm volatile("cp.async.commit_group;");
}
template <int N>
__device__ __forceinline__ void cp_wait() {
    asm volatile("cp.async.wait_group %0;" :: "n"(N));
}
// -(1/x): negation folded into the MUFU operand
__device__ __forceinline__ float nrcp(float x) {
    float y; asm("rcp.approx.f32 %0, %1;" : "=f"(y) : "f"(-x)); return y;
}
__device__ __forceinline__ float fsqrt_fast(float x) {
    float y; asm("sqrt.approx.f32 %0, %1;" : "=f"(y) : "f"(x)); return y;
}

// Levinson-Durbin recursion reading rr from (volatile) shared memory.
// rp points at this thread's 25-float row. Returns K; fills a[0..23].
__device__ __forceinline__ float levdur_smem(const volatile float* rp,
                                             float a[M_ORD]) {
    float E     = rp[0];
    float ninvE = nrcp(E);                     // -1/E, pipelined one iter ahead
    #pragma unroll
    for (int m = 0; m < M_ORD; m++) {
        float acc;
        if (m <= 4) {
            float s0 = rp[m + 1];
            #pragma unroll
            for (int i = 0; i < m; i++) s0 = fmaf(a[i], rp[m - i], s0);
            acc = s0;
        } else if (m <= 10) {
            float s0 = rp[m + 1], s1 = 0.0f;
            #pragma unroll
            for (int i = 0; i + 1 < m; i += 2) {
                s0 = fmaf(a[i    ], rp[m - i    ], s0);
                s1 = fmaf(a[i + 1], rp[m - i - 1], s1);
            }
            if (m & 1) s0 = fmaf(a[m - 1], rp[1], s0);
            acc = s0 + s1;
        } else {
            float s0 = rp[m + 1], s1 = 0.0f, s2 = 0.0f, s3 = 0.0f;
            #pragma unroll
            for (int i = 0; i + 3 < m; i += 4) {
                s0 = fmaf(a[i    ], rp[m - i    ], s0);
                s1 = fmaf(a[i + 1], rp[m - i - 1], s1);
                s2 = fmaf(a[i + 2], rp[m - i - 2], s2);
                s3 = fmaf(a[i + 3], rp[m - i - 3], s3);
            }
            {
                int i = m & ~3;
                if (i     < m) s0 = fmaf(a[i    ], rp[m - i    ], s0);
                if (i + 1 < m) s1 = fmaf(a[i + 1], rp[m - i - 1], s1);
                if (i + 2 < m) s2 = fmaf(a[i + 2], rp[m - i - 2], s2);
            }
            acc = (s0 + s1) + (s2 + s3);
        }

        float k = acc * ninvE;                 // k = -acc/E (MUFU hidden)

        // symmetric in-place update: a_i' = a_i + k * a_{m-1-i}
        #pragma unroll
        for (int i = 0; i < m / 2; i++) {
            float t = a[i];
            float u = a[m - 1 - i];
            a[i]         = fmaf(k, u, t);
            a[m - 1 - i] = fmaf(k, t, u);
        }
        if (m & 1) {
            float t = a[m / 2];
            a[m / 2] = fmaf(k, t, t);
        }
        a[m] = k;

        E     = fmaf(k, acc, E);               // E *= (1 - k^2)
        ninvE = nrcp(E);                       // hides under next dot
    }
    return fsqrt_fast(E);
}

__global__ __launch_bounds__(TPB, 24)          // caps regs at 42 -> 48 warps/SM
void levinson_durbin_kernel(const float* __restrict__ r,
                            float* __restrict__ out,
                            int nrows)
{
    __shared__ float sbuf[WARPS][WTILE_FLOATS];   // 6.4 KB per CTA
    const int lane = threadIdx.x & 31;
    const int wid  = threadIdx.x >> 5;
    const int wrow0 = blockIdx.x * RPB + wid * ROWS_PER_WARP;

    float a[M_ORD];

    if (wrow0 + ROWS_PER_WARP <= nrows) {
        // ---- warp-private async prefetch of its 32-row tile ----
        unsigned s = (unsigned)__cvta_generic_to_shared(&sbuf[wid][0]);
        const float4* g = reinterpret_cast<const float4*>(r + (size_t)wrow0 * NC);
        #pragma unroll
        for (int i = lane; i < WTILE_V4; i += 32) cp_async16(s + i * 16, g + i);
        cp_commit();
        cp_wait<0>();
        __syncwarp();

        // recursion reads rr straight from smem (stride-25: conflict-free)
        const volatile float* rp = &sbuf[wid][lane * NC];
        float Kv = levdur_smem(rp, a);

        // stage output into own row (input row fully consumed by now)
        float* wp = &sbuf[wid][lane * NC];
        wp[0] = Kv;
        #pragma unroll
        for (int i = 0; i < M_ORD; i++) wp[1 + i] = a[i];
        __syncwarp();

        // warp-private coalesced vector store
        float4* o = reinterpret_cast<float4*>(out + (size_t)wrow0 * NC);
        const float4* sb = reinterpret_cast<const float4*>(&sbuf[wid][0]);
        #pragma unroll
        for (int i = lane; i < WTILE_V4; i += 32) o[i] = sb[i];
    } else {
        // generic tail path (not hit for BATCH=262144): registers are fine here
        int row = wrow0 + lane;
        if (row < nrows) {
            float rr[NC];
            #pragma unroll
            for (int i = 0; i < NC; i++) rr[i] = r[(size_t)row * NC + i];
            float E = rr[0];
            float ninvE = nrcp(E);
            #pragma unroll
            for (int m = 0; m < M_ORD; m++) {
                float s0 = rr[m + 1], s1 = 0.0f;
                #pragma unroll
                for (int i = 0; i + 1 < m; i += 2) {
                    s0 = fmaf(a[i    ], rr[m - i    ], s0);
                    s1 = fmaf(a[i + 1], rr[m - i - 1], s1);
                }
                if (m & 1) s0 = fmaf(a[m - 1], rr[1], s0);
                float acc = s0 + s1;
                float k = acc * ninvE;
                #pragma unroll
                for (int i = 0; i < m / 2; i++) {
                    float x = a[i], y = a[m - 1 - i];
                    a[i]         = fmaf(k, y, x);
                    a[m - 1 - i] = fmaf(k, x, y);
                }
                if (m & 1) { float x = a[m / 2]; a[m / 2] = fmaf(k, x, x); }
                a[m] = k;
                E = fmaf(k, acc, E);
                ninvE = nrcp(E);
            }
            out[(size_t)row * NC + 0] = fsqrt_fast(E);
            #pragma unroll
            for (int i = 0; i < M_ORD; i++)
                out[(size_t)row * NC + 1 + i] = a[i];
        }
    }
}

extern "C" void kernel_launch(void* const* d_in, const int* in_sizes, int n_in,
                              void* d_out, int out_size)
{
    const float* r = (const float*)d_in[0];
    float* out = (float*)d_out;
    const int nrows = in_sizes[0] / NC;
    const int grid = (nrows + RPB - 1) / RPB;
    levinson_durbin_kernel<<<grid, TPB>>>(r, out, nrows);
}

// round 11
// speedup vs baseline: 1.2718x; 1.2718x over previous
#include <cuda_runtime.h>
#include <cuda_bf16.h>

// Levinson-Durbin, M=24. ONE row per thread; warp-autonomous 32-row tiles.
// out[row] = [K, a0..a23],  R a = -r1,  K = sqrt(E_24).
//
// R10 = R8 shell (best timed: 56-reg cap, warp-private cp.async staging,
// no __syncthreads) with the dot product simplified to a UNIFORM 2-way
// split. Rationale: occupancy sweeps (R6/R8/R9: occ 38/43/52 -> issue
// 64/65/63) prove extra warps buy nothing; the binding resource is the
// fma pipe (rt=2, ~68% busy). The adaptive 4-way splits spent ~50 extra
// fma-pipe ops/row (join FADDs + tail handling) purely on chain length,
// which resident warps already cover. Removing them cuts fma-pipe work ~8%.

constexpr int M_ORD = 24;
constexpr int NC    = M_ORD + 1;               // 25
constexpr int TPB   = 64;
constexpr int WARPS = TPB / 32;                // 2
constexpr int ROWS_PER_WARP = 32;
constexpr int RPB   = TPB;                     // 64 rows per CTA (32/warp)
constexpr int WTILE_FLOATS = ROWS_PER_WARP * NC;   // 800
constexpr int WTILE_V4     = WTILE_FLOATS / 4;     // 200

__device__ __forceinline__ void cp_async16(unsigned saddr, const void* gaddr) {
    asm volatile("cp.async.cg.shared.global [%0], [%1], 16;"
                 :: "r"(saddr), "l"(gaddr));
}
__device__ __forceinline__ void cp_commit() {
    asm volatile("cp.async.commit_group;");
}
template <int N>
__device__ __forceinline__ void cp_wait() {
    asm volatile("cp.async.wait_group %0;" :: "n"(N));
}
// -(1/x): negation folded into the MUFU operand
__device__ __forceinline__ float nrcp(float x) {
    float y; asm("rcp.approx.f32 %0, %1;" : "=f"(y) : "f"(-x)); return y;
}
__device__ __forceinline__ float fsqrt_fast(float x) {
    float y; asm("sqrt.approx.f32 %0, %1;" : "=f"(y) : "f"(x)); return y;
}

// Full Levinson-Durbin recursion; returns K = sqrt(E_M), fills a[0..23].
// Uniform 2-way split dot: minimal fma-pipe instruction count, chain
// length <= 12 dependent FMAs (covered by co-resident warps).
__device__ __forceinline__ float levdur(const float rr[NC], float a[M_ORD]) {
    float E     = rr[0];
    float ninvE = nrcp(E);                     // -1/E, pipelined one iter ahead
    #pragma unroll
    for (int m = 0; m < M_ORD; m++) {
        // acc = rr[m+1] + sum_i a[i]*rr[m-i]
        float s0 = rr[m + 1];
        float s1 = 0.0f;
        #pragma unroll
        for (int i = 0; i + 1 < m; i += 2) {
            s0 = fmaf(a[i    ], rr[m - i    ], s0);
            s1 = fmaf(a[i + 1], rr[m - i - 1], s1);
        }
        if (m & 1) s0 = fmaf(a[m - 1], rr[1], s0);
        float acc = (m >= 2) ? (s0 + s1) : s0;

        float k = acc * ninvE;                 // k = -acc/E (MUFU hidden)

        // symmetric in-place update: a_i' = a_i + k * a_{m-1-i}
        #pragma unroll
        for (int i = 0; i < m / 2; i++) {
            float t = a[i];
            float u = a[m - 1 - i];
            a[i]         = fmaf(k, u, t);
            a[m - 1 - i] = fmaf(k, t, u);
        }
        if (m & 1) {
            float t = a[m / 2];
            a[m / 2] = fmaf(k, t, t);
        }
        a[m] = k;

        E     = fmaf(k, acc, E);               // E *= (1 - k^2)
        ninvE = nrcp(E);                       // hides under next dot
    }
    return fsqrt_fast(E);
}

__global__ __launch_bounds__(TPB, 18)          // caps regs at 56
void levinson_durbin_kernel(const float* __restrict__ r,
                            float* __restrict__ out,
                            int nrows)
{
    __shared__ float sbuf[WARPS][WTILE_FLOATS];   // 6.4 KB per CTA
    const int lane = threadIdx.x & 31;
    const int wid  = threadIdx.x >> 5;
    const int wrow0 = blockIdx.x * RPB + wid * ROWS_PER_WARP;

    float rr[NC];
    float a[M_ORD];

    if (wrow0 + ROWS_PER_WARP <= nrows) {
        // ---- warp-private async prefetch of its 32-row tile ----
        unsigned s = (unsigned)__cvta_generic_to_shared(&sbuf[wid][0]);
        const float4* g = reinterpret_cast<const float4*>(r + (size_t)wrow0 * NC);
        #pragma unroll
        for (int i = lane; i < WTILE_V4; i += 32) cp_async16(s + i * 16, g + i);
        cp_commit();
        cp_wait<0>();
        __syncwarp();

        // stride-25 (odd) per-thread reads: bank-conflict-free
        #pragma unroll
        for (int i = 0; i < NC; i++) rr[i] = sbuf[wid][lane * NC + i];

        float Kv = levdur(rr, a);

        // stage output into own row (owner-only writes)
        sbuf[wid][lane * NC + 0] = Kv;
        #pragma unroll
        for (int i = 0; i < M_ORD; i++) sbuf[wid][lane * NC + 1 + i] = a[i];
        __syncwarp();

        // warp-private coalesced vector store
        float4* o = reinterpret_cast<float4*>(out + (size_t)wrow0 * NC);
        const float4* sb = reinterpret_cast<const float4*>(&sbuf[wid][0]);
        #pragma unroll
        for (int i = lane; i < WTILE_V4; i += 32) o[i] = sb[i];
    } else {
        // generic tail path (not hit for BATCH=262144)
        int row = wrow0 + lane;
        if (row < nrows) {
            #pragma unroll
            for (int i = 0; i < NC; i++) rr[i] = r[(size_t)row * NC + i];
            float Kv = levdur(rr, a);
            out[(size_t)row * NC + 0] = Kv;
            #pragma unroll
            for (int i = 0; i < M_ORD; i++)
                out[(size_t)row * NC + 1 + i] = a[i];
        }
    }
}

extern "C" void kernel_launch(void* const* d_in, const int* in_sizes, int n_in,
                              void* d_out, int out_size)
{
    const float* r = (const float*)d_in[0];
    float* out = (float*)d_out;
    const int nrows = in_sizes[0] / NC;
    const int grid = (nrows + RPB - 1) / RPB;
    levinson_durbin_kernel<<<grid, TPB>>>(r, out, nrows);
}

// round 12
// speedup vs baseline: 1.3311x; 1.0467x over previous
#include <cuda_runtime.h>
#include <cuda_bf16.h>

// Levinson-Durbin, M=24. ONE row per thread, ONE WARP per CTA, ONE tile.
// out[row] = [K, a0..a23],  R a = -r1,  K = sqrt(E_24).
//
// R11 = R6 shell (TPB=32, 1 tile/CTA, grid 8192 -> shortest CTAs, minimum
// ramp/drain; best measured ncu) + minimal-fma-count dot:
//  - serial accumulation for m<=11 (chain <=44cy, covered by ~8 resident
//    warps/SMSP -- occupancy sweeps R6/R8/R9 proved latency is not binding),
//  - 2-way split only for m>=12 (1 join FADD).
// This trims ~65 fma-pipe ops/row vs the adaptive-split version; the fma
// pipe (rt=2) is the binding resource at ~68% busy.

constexpr int M_ORD = 24;
constexpr int NC    = M_ORD + 1;             // 25
constexpr int TPB   = 32;
constexpr int RPB   = TPB;                   // 32 rows per CTA
constexpr int TILE_FLOATS = RPB * NC;        // 800
constexpr int TILE_V4     = TILE_FLOATS / 4; // 200

__device__ __forceinline__ void cp_async16(unsigned saddr, const void* gaddr) {
    asm volatile("cp.async.cg.shared.global [%0], [%1], 16;"
                 :: "r"(saddr), "l"(gaddr));
}
__device__ __forceinline__ void cp_commit() {
    asm volatile("cp.async.commit_group;");
}
template <int N>
__device__ __forceinline__ void cp_wait() {
    asm volatile("cp.async.wait_group %0;" :: "n"(N));
}
// -(1/x): negation folded into the MUFU operand
__device__ __forceinline__ float nrcp(float x) {
    float y; asm("rcp.approx.f32 %0, %1;" : "=f"(y) : "f"(-x)); return y;
}
__device__ __forceinline__ float fsqrt_fast(float x) {
    float y; asm("sqrt.approx.f32 %0, %1;" : "=f"(y) : "f"(x)); return y;
}

// Full Levinson-Durbin recursion; returns K = sqrt(E_M), fills a[0..23].
// Minimal fma-pipe op count: serial dot for m<=11, 2-way split for m>=12.
__device__ __forceinline__ float levdur(const float rr[NC], float a[M_ORD]) {
    float E     = rr[0];
    float ninvE = nrcp(E);                   // -1/E, pipelined one iter ahead
    #pragma unroll
    for (int m = 0; m < M_ORD; m++) {
        float acc;
        if (m <= 11) {
            // serial single accumulator: zero join overhead
            float s0 = rr[m + 1];
            #pragma unroll
            for (int i = 0; i < m; i++) s0 = fmaf(a[i], rr[m - i], s0);
            acc = s0;
        } else {
            // 2-way split: one join FADD, chain <= 48cy
            float s0 = rr[m + 1], s1 = 0.0f;
            #pragma unroll
            for (int i = 0; i + 1 < m; i += 2) {
                s0 = fmaf(a[i    ], rr[m - i    ], s0);
                s1 = fmaf(a[i + 1], rr[m - i - 1], s1);
            }
            if (m & 1) s0 = fmaf(a[m - 1], rr[1], s0);
            acc = s0 + s1;
        }

        float k = acc * ninvE;               // k = -acc/E (MUFU latency hidden)

        // symmetric in-place update: a_i' = a_i + k * a_{m-1-i}
        #pragma unroll
        for (int i = 0; i < m / 2; i++) {
            float t = a[i];
            float u = a[m - 1 - i];
            a[i]         = fmaf(k, u, t);
            a[m - 1 - i] = fmaf(k, t, u);
        }
        if (m & 1) {
            float t = a[m / 2];
            a[m / 2] = fmaf(k, t, t);
        }
        a[m] = k;

        E     = fmaf(k, acc, E);             // E *= (1 - k^2)
        ninvE = nrcp(E);                     // hides under next dot
    }
    return fsqrt_fast(E);
}

__global__ __launch_bounds__(TPB)
void levinson_durbin_kernel(const float* __restrict__ r,
                            float* __restrict__ out,
                            int nrows)
{
    __shared__ float sbuf[TILE_FLOATS];      // 3.2 KB
    const int tid  = threadIdx.x;
    const int row0 = blockIdx.x * RPB;

    float rr[NC];
    float a[M_ORD];

    if (row0 + RPB <= nrows) {
        // ---- async prefetch of the 32-row tile (coalesced 16B chunks) ----
        unsigned s = (unsigned)__cvta_generic_to_shared(&sbuf[0]);
        const float4* g = reinterpret_cast<const float4*>(r + (size_t)row0 * NC);
        #pragma unroll
        for (int i = tid; i < TILE_V4; i += TPB) cp_async16(s + i * 16, g + i);
        cp_commit();
        cp_wait<0>();
        __syncwarp();

        // stride-25 (odd) per-thread reads: bank-conflict-free
        #pragma unroll
        for (int i = 0; i < NC; i++) rr[i] = sbuf[tid * NC + i];

        float Kv = levdur(rr, a);

        // stage output into own row (owner-only writes)
        sbuf[tid * NC + 0] = Kv;
        #pragma unroll
        for (int i = 0; i < M_ORD; i++) sbuf[tid * NC + 1 + i] = a[i];
        __syncwarp();

        // coalesced vector store
        float4* o = reinterpret_cast<float4*>(out + (size_t)row0 * NC);
        const float4* sb = reinterpret_cast<const float4*>(&sbuf[0]);
        #pragma unroll
        for (int i = tid; i < TILE_V4; i += TPB) o[i] = sb[i];
    } else {
        // generic tail path (not hit for BATCH=262144)
        int row = row0 + tid;
        if (row < nrows) {
            #pragma unroll
            for (int i = 0; i < NC; i++) rr[i] = r[(size_t)row * NC + i];
            float Kv = levdur(rr, a);
            out[(size_t)row * NC + 0] = Kv;
            #pragma unroll
            for (int i = 0; i < M_ORD; i++)
                out[(size_t)row * NC + 1 + i] = a[i];
        }
    }
}

extern "C" void kernel_launch(void* const* d_in, const int* in_sizes, int n_in,
                              void* d_out, int out_size)
{
    const float* r = (const float*)d_in[0];
    float* out = (float*)d_out;
    const int nrows = in_sizes[0] / NC;
    const int grid = (nrows + RPB - 1) / RPB;
    levinson_durbin_kernel<<<grid, TPB>>>(r, out, nrows);
}